// round 8
// baseline (speedup 1.0000x reference)
#include <cuda_runtime.h>
#include <cstdint>
#include <cstddef>

#define NSCORE       256
#define DIM          64
#define N_ITEMS_TOT  500000
#define TILE_N       64
#define NTILES       ((N_ITEMS_TOT + TILE_N - 1) / TILE_N)   // 7813
#define ROWPAD       68                                       // 64 + 4 pad: bank-conflict-free

// ---------------- baseline-PTX helpers (sm_80+, OK on .target sm_103) ----------------
static __device__ __forceinline__ uint32_t f2tf32(float x) {
    uint32_t r;
    asm("cvt.rna.tf32.f32 %0, %1;" : "=r"(r) : "f"(x));
    return r;
}
static __device__ __forceinline__ void mma_tf32(float d[4], const uint32_t a[4],
                                                const uint32_t b0, const uint32_t b1) {
    asm volatile("mma.sync.aligned.m16n8k8.row.col.f32.tf32.tf32.f32 "
                 "{%0,%1,%2,%3}, {%4,%5,%6,%7}, {%8,%9}, {%0,%1,%2,%3};"
                 : "+f"(d[0]), "+f"(d[1]), "+f"(d[2]), "+f"(d[3])
                 : "r"(a[0]), "r"(a[1]), "r"(a[2]), "r"(a[3]), "r"(b0), "r"(b1));
}

// ---------------- persistent state: prologue -> main ----------------
__device__ __align__(16) float g_users[NSCORE * DIM];   // gathered user rows, fp32
__device__ float g_usq[NSCORE];

// Gather the 256 scored users once; fp32 ||u||^2 exactly.
__global__ void cml_prep_users(const int* __restrict__ ids,
                               const float* __restrict__ U) {
    int m = threadIdx.x;                       // 256 threads, one user each
    const float* row = U + (size_t)ids[m] * DIM;
    float s = 0.f;
#pragma unroll 8
    for (int k = 0; k < DIM; k++) {
        float x = row[k];
        g_users[m * DIM + k] = x;
        s = fmaf(x, x, s);
    }
    g_usq[m] = s;
}

// -------- item tile load: coalesced streaming LDG, 4x float4 per thread --------
static __device__ __forceinline__ void ldg_tile(const float* __restrict__ items,
                                                int tile_base, int tid, float4 v[4]) {
    const float4* src = reinterpret_cast<const float4*>(items + (size_t)tile_base * DIM);
#pragma unroll
    for (int j = 0; j < 4; j++) {
        int idx = j * 256 + tid;               // float4 index within tile (1024 total)
        int r = idx >> 4;                      // local item row (16 float4 per row)
        if (tile_base + r < N_ITEMS_TOT) v[j] = __ldcs(src + idx);
        else v[j] = make_float4(0.f, 0.f, 0.f, 0.f);
    }
}

// -------- tile -> smem: tf32-cvt, padded STS; fp32 i_sq via 16-lane shfl --------
static __device__ __forceinline__ void sts_tile(const float4 v[4], float* __restrict__ it,
                                                float* __restrict__ isq, int tid) {
#pragma unroll
    for (int j = 0; j < 4; j++) {
        float4 x = v[j];
        int idx = j * 256 + tid;
        int r = idx >> 4;
        int d = (idx & 15) * 4;
        // exact fp32 partial |i|^2, reduced over the 16 lanes sharing row r
        float p = fmaf(x.x, x.x, fmaf(x.y, x.y, fmaf(x.z, x.z, x.w * x.w)));
        p += __shfl_xor_sync(0xffffffffu, p, 8);
        p += __shfl_xor_sync(0xffffffffu, p, 4);
        p += __shfl_xor_sync(0xffffffffu, p, 2);
        p += __shfl_xor_sync(0xffffffffu, p, 1);
        if ((tid & 15) == 0) isq[r] = p;
        uint4 t;
        t.x = f2tf32(x.x); t.y = f2tf32(x.y); t.z = f2tf32(x.z); t.w = f2tf32(x.w);
        *reinterpret_cast<uint4*>(it + r * ROWPAD + d) = t;   // 16B-aligned (ROWPAD*4 % 16 == 0)
    }
}

__global__ void __launch_bounds__(256, 1)
cml_main(const float* __restrict__ items, float* __restrict__ out) {
    __shared__ float sm_it[2][TILE_N * ROWPAD];   // 2 x 17408 B, tf32-rounded item tiles
    __shared__ float sm_isq[2][TILE_N];

    int tid = threadIdx.x, wid = tid >> 5, lane = tid & 31;
    int grp = lane >> 2, tig = lane & 3;
    int mbase = wid * 32;                          // 8 warps x 32 user-rows = 256

    // ---- A fragments (users, tf32) resident in registers for the whole kernel ----
    // A[mf][ks][reg]: reg0:(r, c) reg1:(r+8, c) reg2:(r, c+4) reg3:(r+8, c+4)
    uint32_t A[2][8][4];
    float nu[2][2];                                // -usq for the 4 rows this thread owns
#pragma unroll
    for (int mf = 0; mf < 2; mf++) {
        int r0 = mbase + mf * 16 + grp;
#pragma unroll
        for (int ks = 0; ks < 8; ks++) {
            int c = ks * 8 + tig;
            A[mf][ks][0] = f2tf32(g_users[r0 * DIM + c]);
            A[mf][ks][1] = f2tf32(g_users[(r0 + 8) * DIM + c]);
            A[mf][ks][2] = f2tf32(g_users[r0 * DIM + c + 4]);
            A[mf][ks][3] = f2tf32(g_users[(r0 + 8) * DIM + c + 4]);
        }
        nu[mf][0] = -g_usq[r0];
        nu[mf][1] = -g_usq[r0 + 8];
    }

    int bx = blockIdx.x, G = gridDim.x;
    int cnt = (NTILES - bx + G - 1) / G;

    float4 v[4];
    ldg_tile(items, bx * TILE_N, tid, v);
    sts_tile(v, sm_it[0], sm_isq[0], tid);
    __syncthreads();

    for (int i = 0; i < cnt; i++) {
        int cur = i & 1, nxt = cur ^ 1;
        int tile_base = (bx + i * G) * TILE_N;

        if (i + 1 < cnt) ldg_tile(items, (bx + (i + 1) * G) * TILE_N, tid, v);

        // ---- MMA: cross[u, n] over this 64-item tile ----
        float C[2][8][4];
#pragma unroll
        for (int mf = 0; mf < 2; mf++)
#pragma unroll
            for (int ni = 0; ni < 8; ni++)
#pragma unroll
                for (int q = 0; q < 4; q++) C[mf][ni][q] = 0.f;

        const uint32_t* st = reinterpret_cast<const uint32_t*>(sm_it[cur]);
        // Software-pipelined B loads: fetch ks-step k+1's operands while MMAing step k.
        uint32_t Bc[8][2], Bn[8][2];
#pragma unroll
        for (int ni = 0; ni < 8; ni++) {
            int noff = (ni * 8 + grp) * ROWPAD + tig;        // ks = 0
            Bc[ni][0] = st[noff];
            Bc[ni][1] = st[noff + 4];
        }
#pragma unroll
        for (int ks = 0; ks < 8; ks++) {
            if (ks + 1 < 8) {
                int koff = (ks + 1) * 8 + tig;
#pragma unroll
                for (int ni = 0; ni < 8; ni++) {
                    int noff = (ni * 8 + grp) * ROWPAD + koff;   // conflict-free: 68 % 32 = 4
                    Bn[ni][0] = st[noff];
                    Bn[ni][1] = st[noff + 4];
                }
            }
#pragma unroll
            for (int ni = 0; ni < 8; ni++) {
                mma_tf32(C[0][ni], A[0][ks], Bc[ni][0], Bc[ni][1]);
                mma_tf32(C[1][ni], A[1][ks], Bc[ni][0], Bc[ni][1]);
            }
#pragma unroll
            for (int ni = 0; ni < 8; ni++) {
                Bc[ni][0] = Bn[ni][0];
                Bc[ni][1] = Bn[ni][1];
            }
        }

        // Stage nxt is free: every warp's MMA on it finished before last iteration's barrier.
        if (i + 1 < cnt) sts_tile(v, sm_it[nxt], sm_isq[nxt], tid);

        // ---- epilogue: score = 2*cross - usq - isq, streaming float2 stores ----
        const float* isq = sm_isq[cur];
#pragma unroll
        for (int mf = 0; mf < 2; mf++) {
            int r0 = mbase + mf * 16 + grp;
            float* row0 = out + (size_t)r0 * N_ITEMS_TOT;
            float* row1 = out + (size_t)(r0 + 8) * N_ITEMS_TOT;
#pragma unroll
            for (int ni = 0; ni < 8; ni++) {
                int cl = ni * 8 + 2 * tig;
                int col = tile_base + cl;
                if (col < N_ITEMS_TOT) {
                    float2 iq = *reinterpret_cast<const float2*>(isq + cl);
                    float2 s0, s1;
                    s0.x = fmaf(2.f, C[mf][ni][0], nu[mf][0] - iq.x);
                    s0.y = fmaf(2.f, C[mf][ni][1], nu[mf][0] - iq.y);
                    s1.x = fmaf(2.f, C[mf][ni][2], nu[mf][1] - iq.x);
                    s1.y = fmaf(2.f, C[mf][ni][3], nu[mf][1] - iq.y);
                    __stcs(reinterpret_cast<float2*>(row0 + col), s0);
                    __stcs(reinterpret_cast<float2*>(row1 + col), s1);
                }
            }
        }
        __syncthreads();
    }
}

extern "C" void kernel_launch(void* const* d_in, const int* in_sizes, int n_in,
                              void* d_out, int out_size) {
    (void)in_sizes; (void)n_in; (void)out_size;
    const int*   ids   = (const int*)d_in[0];
    const float* users = (const float*)d_in[1];
    const float* items = (const float*)d_in[2];
    float*       out   = (float*)d_out;

    int sms = 148;
    cudaDeviceGetAttribute(&sms, cudaDevAttrMultiProcessorCount, 0);
    int grid = sms < NTILES ? sms : NTILES;

    cml_prep_users<<<1, 256>>>(ids, users);
    cml_main<<<grid, 256>>>(items, out);
}